// round 2
// baseline (speedup 1.0000x reference)
#include <cuda_runtime.h>
#include <cstdint>

#define T_STEPS 256
#define BATCH   64
#define HID     512
#define OUTD    4

// Recurrence decomposition: 4 batch groups x 32 column-slice CTAs = 128 CTAs
#define GB 4
#define GJ 32
#define RH (BATCH / GB)   // 16 rows per group
#define CJ (HID / GJ)     // 16 cols per CTA

// Device-global scratch (no cudaMalloc allowed)
__device__ __align__(16) float g_xw[T_STEPS * BATCH * HID];   // [T][B][H]
__device__ __align__(16) float g_h[2][BATCH][HID];            // double-buffered h
__device__ unsigned int g_flags[GB][GJ];                      // monotonic counters

__device__ __forceinline__ unsigned int ld_acquire_u32(const unsigned int* p) {
    unsigned int v;
    asm volatile("ld.acquire.gpu.global.u32 %0, [%1];" : "=r"(v) : "l"(p) : "memory");
    return v;
}
__device__ __forceinline__ void st_release_u32(unsigned int* p, unsigned int v) {
    asm volatile("st.release.gpu.global.u32 [%0], %1;" :: "l"(p), "r"(v) : "memory");
}

// Accurate even under --use_fast_math (expf -> __expf ~2^-21 rel error).
__device__ __forceinline__ float tanh_accurate(float z) {
    return 1.0f - 2.0f / (expf(2.0f * z) + 1.0f);
}

// ---------------------------------------------------------------------------
// Kernel 1: g_xw[t][b][:] = emb[x[b][t]] @ W_ih^T + b_ih
// 64x64 tile over K=512, BK=16, 256 threads, 4x4 microtile.
// ---------------------------------------------------------------------------
__global__ void proj_kernel(const int* __restrict__ x,
                            const float* __restrict__ emb,
                            const float* __restrict__ W_ih,
                            const float* __restrict__ b_ih)
{
    __shared__ float As[16][64];
    __shared__ float Bs[16][64];
    __shared__ int   idx[64];

    const int tid = threadIdx.x;
    const int m0 = blockIdx.y * 64;   // row = b*T + t
    const int j0 = blockIdx.x * 64;   // hidden column

    if (tid < 64) idx[tid] = x[m0 + tid];
    __syncthreads();

    const int lm = tid >> 2;   // load row 0..63
    const int lq = tid & 3;    // float4 slot in 16-wide k panel
    const int ty = tid >> 4;   // 0..15
    const int tx = tid & 15;   // 0..15

    float acc[4][4];
#pragma unroll
    for (int i = 0; i < 4; ++i)
#pragma unroll
        for (int j = 0; j < 4; ++j) acc[i][j] = 0.0f;

    const size_t arow = (size_t)idx[lm] * HID;
    const size_t brow = (size_t)(j0 + lm) * HID;

    for (int k0 = 0; k0 < HID; k0 += 16) {
        float4 av = *(const float4*)(emb  + arow + k0 + 4 * lq);
        float4 bv = *(const float4*)(W_ih + brow + k0 + 4 * lq);
        As[4*lq+0][lm] = av.x; As[4*lq+1][lm] = av.y;
        As[4*lq+2][lm] = av.z; As[4*lq+3][lm] = av.w;
        Bs[4*lq+0][lm] = bv.x; Bs[4*lq+1][lm] = bv.y;
        Bs[4*lq+2][lm] = bv.z; Bs[4*lq+3][lm] = bv.w;
        __syncthreads();

#pragma unroll
        for (int k = 0; k < 16; ++k) {
            float a[4], b[4];
            *(float4*)a = *(const float4*)(&As[k][4 * ty]);
            *(float4*)b = *(const float4*)(&Bs[k][4 * tx]);
#pragma unroll
            for (int i = 0; i < 4; ++i)
#pragma unroll
                for (int j = 0; j < 4; ++j)
                    acc[i][j] += a[i] * b[j];
        }
        __syncthreads();
    }

    float4 bi = *(const float4*)(b_ih + j0 + 4 * tx);
#pragma unroll
    for (int i = 0; i < 4; ++i) {
        int m = m0 + 4 * ty + i;
        int b = m >> 8;      // T = 256
        int t = m & 255;
        float4 v;
        v.x = acc[i][0] + bi.x; v.y = acc[i][1] + bi.y;
        v.z = acc[i][2] + bi.z; v.w = acc[i][3] + bi.w;
        *(float4*)(&g_xw[((size_t)t * BATCH + b) * HID + j0 + 4 * tx]) = v;
    }
}

// ---------------------------------------------------------------------------
// Kernel 2: persistent recurrence + FC. 128 CTAs x 256 threads.
// Thread (j = tid&15, kc = tid>>4) holds W_hh[j0+j][32*kc..+31] in registers.
// ---------------------------------------------------------------------------
__global__ void rec_kernel(const float* __restrict__ W_hh,
                           const float* __restrict__ b_hh,
                           const float* __restrict__ W_fc,
                           const float* __restrict__ b_fc,
                           float* __restrict__ out)
{
    __shared__ float hs[RH * HID];          // 16x512 h rows (32 KB)
    __shared__ float psum[RH * 16 * 17];    // [row][kc][j] padded

    const int tid = threadIdx.x;
    const int g  = blockIdx.x >> 5;
    const int jg = blockIdx.x & 31;
    const int r0 = g * RH;
    const int j0 = jg * CJ;

    const int j  = tid & 15;    // compute: column within slice
    const int kc = tid >> 4;    // compute: 32-wide k chunk
    const int rr = tid >> 4;    // reduce: row
    const int jj = tid & 15;    // reduce: column

    // W_hh slice to registers (reused 256 steps x 16 rows)
    float wreg[32];
    {
        const float* wrow = W_hh + (size_t)(j0 + j) * HID + kc * 32;
#pragma unroll
        for (int q = 0; q < 8; ++q) {
            float4 v = *(const float4*)(wrow + 4 * q);
            wreg[4*q+0] = v.x; wreg[4*q+1] = v.y;
            wreg[4*q+2] = v.z; wreg[4*q+3] = v.w;
        }
    }
    const float bhh = b_hh[j0 + jj];

    // Initialize out with bias (one CTA per group).
    if (jg == 0 && tid < RH * OUTD) {
        int r = tid >> 2, o = tid & 3;
        out[(r0 + r) * OUTD + o] = b_fc[o];
    }

    // Monotonic flag base (single writer per flag; survives graph replays).
    const unsigned int base = g_flags[g][jg];

    // Production 0: h0 = 0.
    g_h[0][r0 + rr][j0 + jj] = 0.0f;
    __threadfence();
    __syncthreads();
    if (tid == 0) st_release_u32(&g_flags[g][jg], base + 1u);

    float hval = 0.0f;

    for (int p = 1; p <= T_STEPS; ++p) {
        if (tid < GJ) {
            const unsigned int tgt = base + (unsigned int)p;
            while (ld_acquire_u32(&g_flags[g][tid]) < tgt) { }
        }
        __syncthreads();

        const float xwv = g_xw[((size_t)(p - 1) * BATCH + (r0 + rr)) * HID + j0 + jj];

        // Fill hs with this group's h_{p-1} rows (16x512 contiguous).
        {
            const float4* hsrc = (const float4*)(&g_h[(p - 1) & 1][r0][0]);
            float4* hdst = (float4*)hs;
#pragma unroll
            for (int i = 0; i < 8; ++i)
                hdst[tid + 256 * i] = hsrc[tid + 256 * i];
        }
        __syncthreads();

        // Partial dot products over this thread's 32-wide k chunk, 16 rows.
#pragma unroll
        for (int r = 0; r < RH; ++r) {
            const float4* hrow = (const float4*)(hs + r * HID + kc * 32);
            float a = 0.0f;
#pragma unroll
            for (int q = 0; q < 8; ++q) {
                float4 hv = hrow[q];
                a += hv.x * wreg[4*q+0] + hv.y * wreg[4*q+1]
                   + hv.z * wreg[4*q+2] + hv.w * wreg[4*q+3];
            }
            psum[r * 272 + kc * 17 + j] = a;
        }
        __syncthreads();

        // Reduce 16 partials, add xw + bias, tanh, publish.
        float z = bhh + xwv;
#pragma unroll
        for (int c = 0; c < 16; ++c)
            z += psum[rr * 272 + c * 17 + jj];
        hval = tanh_accurate(z);
        g_h[p & 1][r0 + rr][j0 + jj] = hval;
        __threadfence();
        __syncthreads();
        if (tid == 0) st_release_u32(&g_flags[g][jg], base + (unsigned int)p + 1u);
    }

    // FC: out[b][o] += sum over this slice of hT * W_fc. hval = hT(r0+rr, j0+jj).
    float partial[OUTD];
#pragma unroll
    for (int o = 0; o < OUTD; ++o)
        partial[o] = hval * W_fc[o * HID + j0 + jj];
#pragma unroll
    for (int o = 0; o < OUTD; ++o)
#pragma unroll
        for (int s = 8; s > 0; s >>= 1)
            partial[o] += __shfl_xor_sync(0xFFFFFFFFu, partial[o], s);
    if (jj == 0) {
#pragma unroll
        for (int o = 0; o < OUTD; ++o)
            atomicAdd(&out[(r0 + rr) * OUTD + o], partial[o]);
    }
}

extern "C" void kernel_launch(void* const* d_in, const int* in_sizes, int n_in,
                              void* d_out, int out_size)
{
    const int*   x    = (const int*)  d_in[0];
    const float* emb  = (const float*)d_in[1];
    const float* W_ih = (const float*)d_in[2];
    const float* W_hh = (const float*)d_in[3];
    const float* b_ih = (const float*)d_in[4];
    const float* b_hh = (const float*)d_in[5];
    const float* W_fc = (const float*)d_in[6];
    const float* b_fc = (const float*)d_in[7];
    float* out = (float*)d_out;
    (void)in_sizes; (void)n_in; (void)out_size;

    proj_kernel<<<dim3(HID / 64, (BATCH * T_STEPS) / 64), 256>>>(x, emb, W_ih, b_ih);
    rec_kernel<<<GB * GJ, 256>>>(W_hh, b_hh, W_fc, b_fc, out);
}